// round 8
// baseline (speedup 1.0000x reference)
#include <cuda_runtime.h>
#include <cuda_bf16.h>
#include <math.h>

// Problem constants
#define BB   2048      // batch
#define TT   128       // time
#define DD   20        // input dim
#define HH   128       // hidden
#define G4   512       // 4*H
#define TM1  127       // T-1 steps
#define XT_ELEMS ((size_t)BB * TM1 * DD)

// LSTM kernel tiling
#define NB    16       // batches per block
#define NTH   512      // threads: 2 gate rows x 4 batch-pairs each
#define KS    88       // k-slices of W resident in smem (16B-aligned tail start)
#define KR    40       // k-slices streamed from global/L2 per step
#define HPAD  20       // hs row stride (k-major [k][bb]); 80B rows, 16B-aligned sublanes
#define GPU64 520      // gs row stride in u64 (8 pairs x 520)

// Scratch: precomputed input-side gate contributions, PAIR-INTERLEAVED:
// element (b, t, j) -> g_Gx[ ((b>>1)*TM1*G4 + t*G4 + j)*2 + (b&1) ]
__device__ float g_Gx[BB * TM1 * G4];

// ---------------------------------------------------------------------------
// fast transcendentals (error ~1e-6, threshold is 1e-3)
// ---------------------------------------------------------------------------
__device__ __forceinline__ float sigf(float x) {
    return __fdividef(1.f, 1.f + __expf(-x));
}
__device__ __forceinline__ float tanhfast(float x) {
    return fmaf(2.f, __fdividef(1.f, 1.f + __expf(-2.f * x)), -1.f);
}

__device__ __forceinline__ unsigned long long dup2(float a) {
    unsigned long long r;
    asm("mov.b64 %0, {%1, %1};" : "=l"(r) : "r"(__float_as_uint(a)));
    return r;
}
__device__ __forceinline__ void fma2(unsigned long long& d, unsigned long long a, unsigned long long b) {
    asm("fma.rn.f32x2 %0, %1, %2, %0;" : "+l"(d) : "l"(a), "l"(b));
}

// ---------------------------------------------------------------------------
// Kernel 1: alpha = softmax(xw) (time-invariant by softmax shift-invariance),
// X_tilde, and G_x = X_tilde@W_ih^T + b_ih + b_hh. One block per batch.
// ---------------------------------------------------------------------------
__global__ __launch_bounds__(256) void prep_kernel(
    const float* __restrict__ X,       // [B][T][D]
    const float* __restrict__ W_attn,  // [1][2H+T]
    const float* __restrict__ W_ih,    // [4H][D]
    const float* __restrict__ b_ih,    // [4H]
    const float* __restrict__ b_hh,    // [4H]
    float* __restrict__ out)           // X_tilde region: [B][T-1][D]
{
    extern __shared__ float sm[];
    float* Xs   = sm;                  // [T*D] = 2560
    float* Wih  = Xs + TT * DD;        // [512*21]
    float* bias = Wih + G4 * 21;       // [512]
    float* wxs  = bias + G4;           // [128]
    float* alpha = wxs + TT;           // [32]

    const int b = blockIdx.x;
    const int tid = threadIdx.x;
    const float* Xb = X + (size_t)b * TT * DD;

    for (int i = tid; i < TT * DD; i += 256) Xs[i] = Xb[i];
    for (int i = tid; i < TT; i += 256) wxs[i] = W_attn[2 * HH + i];
    for (int i = tid; i < G4; i += 256) bias[i] = b_ih[i] + b_hh[i];
    for (int i = tid; i < G4 * DD; i += 256) {
        int j = i / DD, d = i % DD;
        Wih[j * 21 + d] = W_ih[i];
    }
    __syncthreads();

    if (tid < DD) {
        float s = 0.f;
        for (int t = 0; t < TT; t++) s += Xs[t * DD + tid] * wxs[t];
        alpha[tid] = s;
    }
    __syncthreads();
    if (tid == 0) {
        float mx = alpha[0];
        for (int d = 1; d < DD; d++) mx = fmaxf(mx, alpha[d]);
        float e[DD];
        float ssum = 0.f;
        for (int d = 0; d < DD; d++) { e[d] = expf(alpha[d] - mx); ssum += e[d]; }
        float inv = 1.f / ssum;
        for (int d = 0; d < DD; d++) alpha[d] = e[d] * inv;
    }
    __syncthreads();

    float* outXt = out + (size_t)b * TM1 * DD;
    for (int i = tid; i < TM1 * DD; i += 256) {
        int d = i % DD;
        float v = alpha[d] * Xs[i];
        Xs[i] = v;
        outXt[i] = v;
    }
    __syncthreads();

    // pair-interleaved G_x write
    float* Gxb = g_Gx + ((size_t)(b >> 1) * TM1 * G4) * 2 + (b & 1);
    for (int t = 0; t < TM1; t++) {
        float x[DD];
#pragma unroll
        for (int d = 0; d < DD; d++) x[d] = Xs[t * DD + d];
#pragma unroll
        for (int j0 = 0; j0 < G4; j0 += 256) {
            int j = j0 + tid;
            float acc = bias[j];
#pragma unroll
            for (int d = 0; d < DD; d++) acc += x[d] * Wih[j * 21 + d];
            Gxb[((size_t)t * G4 + j) * 2] = acc;
        }
    }
}

// ---------------------------------------------------------------------------
// Kernel 2: persistent LSTM recurrence, FFMA2-packed batch pairs.
// 128 blocks x 512 threads. Thread (jg = tid&255, pg = tid>>8) owns gate rows
// jg and jg+256 for batch pairs 4pg..4pg+3.
// W: k<KS in smem (j-paired float2), k>=KS streamed from L2 (float4 pipeline).
// ---------------------------------------------------------------------------
__global__ __launch_bounds__(NTH, 1) void lstm_kernel(
    const float* __restrict__ W_hh,    // [4H][H] row-major
    float* __restrict__ out)
{
    extern __shared__ float sm[];
    float* Wlo = sm;                              // [KS][512] j-paired: [k][jg][rr]
    float* hs  = Wlo + KS * 512;                  // [128][HPAD]  k-major h
    unsigned long long* gsu =
        reinterpret_cast<unsigned long long*>(hs + 128 * HPAD);  // [8][GPU64] u64 gates

    const int tid  = threadIdx.x;
    const int wid  = tid >> 5;
    const int lane = tid & 31;
    const int jg   = tid & 255;
    const int pg   = tid >> 8;        // pair group: pairs 4pg..4pg+3
    const int j0   = jg;
    const int j1   = jg + 256;
    const int b0   = blockIdx.x * NB;

    // ---- prologue: load W k<KS into smem, j-paired layout ----
    // Wlo[k*512 + jg*2 + rr] = W_hh[(jg + 256*rr)*HH + k]
    for (int row = wid; row < 512; row += 16) {
        for (int k = lane; k < KS; k += 32) {
            Wlo[k * 512 + (row & 255) * 2 + (row >> 8)] = W_hh[row * HH + k];
        }
    }
    for (int i = tid; i < 128 * HPAD; i += NTH) hs[i] = 0.f;
    float creg[4];
#pragma unroll
    for (int p = 0; p < 4; p++) creg[p] = 0.f;
    __syncthreads();

    // G_x base (pair-interleaved)
    const int q0 = blockIdx.x * (NB / 2);
    const unsigned long long* Gx64 = reinterpret_cast<const unsigned long long*>(g_Gx);

    float* outE = out + XT_ELEMS;

    // W tail pointers (16B aligned: KS*4 = 352 B)
    const float4* w0p = reinterpret_cast<const float4*>(W_hh + j0 * HH + KS);
    const float4* w1p = reinterpret_cast<const float4*>(W_hh + j1 * HH + KS);

    // prefetch G_x for t=0: gxb[rr][pp]
    unsigned long long gxb[2][4];
#pragma unroll
    for (int pp = 0; pp < 4; pp++) {
        size_t base = (size_t)(q0 + 4 * pg + pp) * TM1 * G4;
        gxb[0][pp] = Gx64[base + j0];
        gxb[1][pp] = Gx64[base + j1];
    }

    const int m_cell = tid & (HH - 1);
    const int bb_base = tid >> 7;     // 0..3

    for (int t = 0; t < TM1; t++) {
        // ---- acc init from prefetched G_x ----
        unsigned long long acc[2][4];
#pragma unroll
        for (int rr = 0; rr < 2; rr++)
#pragma unroll
            for (int pp = 0; pp < 4; pp++) acc[rr][pp] = gxb[rr][pp];

        // ---- issue next step's G_x loads (hidden under GEMM) ----
        if (t + 1 < TM1) {
#pragma unroll
            for (int pp = 0; pp < 4; pp++) {
                size_t base = (size_t)(q0 + 4 * pg + pp) * TM1 * G4 + (size_t)(t + 1) * G4;
                gxb[0][pp] = Gx64[base + j0];
                gxb[1][pp] = Gx64[base + j1];
            }
        }

        // ---- GEMM part 1: k < KS from smem ----
#pragma unroll 4
        for (int k = 0; k < KS; k++) {
            float2 w = *reinterpret_cast<const float2*>(Wlo + k * 512 + jg * 2);
            unsigned long long w0 = dup2(w.x);
            unsigned long long w1 = dup2(w.y);
            const ulonglong2* hp = reinterpret_cast<const ulonglong2*>(hs + k * HPAD + 8 * pg);
            ulonglong2 ha = hp[0];
            ulonglong2 hb = hp[1];
            fma2(acc[0][0], w0, ha.x); fma2(acc[1][0], w1, ha.x);
            fma2(acc[0][1], w0, ha.y); fma2(acc[1][1], w1, ha.y);
            fma2(acc[0][2], w0, hb.x); fma2(acc[1][2], w1, hb.x);
            fma2(acc[0][3], w0, hb.y); fma2(acc[1][3], w1, hb.y);
        }

        // ---- GEMM part 2: k >= KS, W streamed from L2 (distance-1 float4 pipe) ----
        {
            float4 w0c = w0p[0];
            float4 w1c = w1p[0];
#pragma unroll
            for (int c = 0; c < KR / 4; c++) {
                float4 w0n, w1n;
                if (c + 1 < KR / 4) { w0n = w0p[c + 1]; w1n = w1p[c + 1]; }
#pragma unroll
                for (int kk = 0; kk < 4; kk++) {
                    int k = KS + c * 4 + kk;
                    float wa = (kk == 0) ? w0c.x : (kk == 1) ? w0c.y : (kk == 2) ? w0c.z : w0c.w;
                    float wb = (kk == 0) ? w1c.x : (kk == 1) ? w1c.y : (kk == 2) ? w1c.z : w1c.w;
                    unsigned long long u0 = dup2(wa);
                    unsigned long long u1 = dup2(wb);
                    const ulonglong2* hp = reinterpret_cast<const ulonglong2*>(hs + k * HPAD + 8 * pg);
                    ulonglong2 ha = hp[0];
                    ulonglong2 hb = hp[1];
                    fma2(acc[0][0], u0, ha.x); fma2(acc[1][0], u1, ha.x);
                    fma2(acc[0][1], u0, ha.y); fma2(acc[1][1], u1, ha.y);
                    fma2(acc[0][2], u0, hb.x); fma2(acc[1][2], u1, hb.x);
                    fma2(acc[0][3], u0, hb.y); fma2(acc[1][3], u1, hb.y);
                }
                w0c = w0n; w1c = w1n;
            }
        }

        // ---- stage gates gsu[pair][j] (u64, conflict-free) ----
#pragma unroll
        for (int pp = 0; pp < 4; pp++) {
            unsigned long long* gp = gsu + (size_t)(4 * pg + pp) * GPU64;
            gp[j0] = acc[0][pp];
            gp[j1] = acc[1][pp];
        }
        __syncthreads();

        // ---- LSTM cell: 2048 cells, 4 per thread ----
        const float* gsf = reinterpret_cast<const float*>(gsu);
#pragma unroll
        for (int pp = 0; pp < 4; pp++) {
            int bb = bb_base + 4 * pp;
            int pr = bb >> 1;
            int half = bb & 1;
            const float* gp = gsf + (size_t)pr * (GPU64 * 2) + half;
            float i_ = gp[(m_cell      ) * 2];
            float f_ = gp[(m_cell + 128) * 2];
            float g_ = gp[(m_cell + 256) * 2];
            float o_ = gp[(m_cell + 384) * 2];
            float si = sigf(i_);
            float sf = sigf(f_);
            float so = sigf(o_);
            float tg = tanhfast(g_);
            float cn = fmaf(sf, creg[pp], si * tg);
            float hn = so * tanhfast(cn);
            creg[pp] = cn;
            hs[m_cell * HPAD + bb] = hn;
            outE[((size_t)(b0 + bb) * TM1 + t) * HH + m_cell] = hn;
        }
        __syncthreads();   // hs complete before next step's GEMM reads
    }
}

// ---------------------------------------------------------------------------
extern "C" void kernel_launch(void* const* d_in, const int* in_sizes, int n_in,
                              void* d_out, int out_size)
{
    const float* X      = (const float*)d_in[0];
    const float* W_attn = (const float*)d_in[1];
    // d_in[2] = b_attn: dead (softmax shift invariance)
    const float* W_ih   = (const float*)d_in[3];
    const float* W_hh   = (const float*)d_in[4];
    const float* b_ih   = (const float*)d_in[5];
    const float* b_hh   = (const float*)d_in[6];
    float* out = (float*)d_out;

    const int smem1 = (TT * DD + G4 * 21 + G4 + TT + 32) * 4;              // 55,936 B
    const int smem2 = (KS * 512 + 128 * HPAD) * 4 + 8 * GPU64 * 8;         // 223,744 B

    cudaFuncSetAttribute(prep_kernel, cudaFuncAttributeMaxDynamicSharedMemorySize, smem1);
    cudaFuncSetAttribute(lstm_kernel, cudaFuncAttributeMaxDynamicSharedMemorySize, smem2);

    prep_kernel<<<BB, 256, smem1>>>(X, W_attn, W_ih, b_ih, b_hh, out);
    lstm_kernel<<<BB / NB, NTH, smem2>>>(W_hh, out);
}